// round 2
// baseline (speedup 1.0000x reference)
#include <cuda_runtime.h>
#include <math.h>

#define B_SZ   8
#define L_SZ   2048
#define D_HALF 256
#define D_TYPE 32
#define HID    544          // 512 positional + 32 type
#define TI     32
#define TJ     128

// fp32 constant matching reference: -log(10000.0)/512 rounded to f32
#define DIV_C  (-0.017988946f)

// -------- hidden vector: sin/cos(arc+phi) + type embedding --------
__global__ void __launch_bounds__(256) hidden_kernel(
    const int* __restrict__ etype,
    const float* __restrict__ etime,
    const float* __restrict__ Wt,
    const float* __restrict__ temb,
    float* __restrict__ out_hidden) {
    int bl = blockIdx.x;                 // b*L + l
    int k  = threadIdx.x;                // 0..255
    int l  = bl & (L_SZ - 1);

    // div_term exactly like reference: f32 exp of f32 product
    float dv  = expf((float)(2 * k) * DIV_C);
    float t   = etime[bl];
    float arc = (float)l * dv;           // same fp32 product as reference
    float x   = arc + t * Wt[k];

    // Cody-Waite reduction x mod 2*pi  (|x| < 2100, n < 340)
    float n = rintf(x * 0.15915494309189535f);
    float r = fmaf(n, -6.28125f, x);                    // C1 exact in binary
    r = fmaf(n, -1.9353071795864769e-3f, r);            // C2
    float s, c;
    __sincosf(r, &s, &c);

    float* o = out_hidden + (size_t)bl * HID;
    o[k]           = s;
    o[D_HALF + k]  = c;
    if (k < D_TYPE)
        o[2 * D_HALF + k] = temb[etype[bl] * D_TYPE + k];
}

// -------- scores + t_diff --------
__device__ __forceinline__ float score1(float d, float paj, float gaj,
                                        float pbi, float gbi,
                                        float BLv, float BGv) {
    float xl = paj + pbi + BLv;
    // softplus(xl) = max(xl,0) + log1p(exp(-|xl|))
    float sp = fmaxf(xl, 0.f) + __logf(1.f + __expf(-fabsf(xl)));
    float rl = __fdividef(1.f, sp + 1e-6f);
    float u  = d * rl;
    float kk = 0.4f * __expf(-0.5f * u * u) + 0.3f * __expf(-u);
    float xg = 5.f * (gaj + gbi + BGv);
    float g  = __fdividef(1.f, 1.f + __expf(-xg));
    return g * kk;
}

__global__ void __launch_bounds__(256) pair_kernel(
    const int* __restrict__ etype,
    const float* __restrict__ etime,
    const float* __restrict__ temb,
    const float* __restrict__ wl,
    const float* __restrict__ wg,
    const float* __restrict__ p_bl,
    const float* __restrict__ p_bg,
    float* __restrict__ out_scores,
    float* __restrict__ out_tdiff) {

    int b  = blockIdx.z;
    int i0 = blockIdx.y * TI;
    int j0 = blockIdx.x * TJ;

    __shared__ float s_tj[TJ], s_paj[TJ], s_gaj[TJ];
    __shared__ float s_ti[TI], s_pbi[TI], s_gbi[TI];

    int tid = threadIdx.x;
    int off = b * L_SZ;

    bool zero_tile = (j0 >= i0 + TI);      // entire tile has j >= i -> scores 0
    bool full_tile = (j0 + TJ <= i0);      // entire tile has j <  i -> no mask

    // ---- fill smem: times + fused per-row dot products (replaces prep kernel)
    if (tid < TJ) {
        int j = j0 + tid;
        s_tj[tid] = etime[off + j];
        if (!zero_tile) {
            int et = etype[off + j];
            const float* te = temb + et * D_TYPE;
            float pa = 0.f, ga = 0.f;
#pragma unroll
            for (int k = 0; k < D_TYPE; ++k) {
                float v = te[k];
                pa += v * wl[k];
                ga += v * wg[k];
            }
            s_paj[tid] = pa; s_gaj[tid] = ga;
        }
    } else if (tid < TJ + TI) {
        int il = tid - TJ;
        int i  = i0 + il;
        s_ti[il] = etime[off + i];
        if (!zero_tile) {
            int et = etype[off + i];
            const float* te = temb + et * D_TYPE;
            float pb = 0.f, gb = 0.f;
#pragma unroll
            for (int k = 0; k < D_TYPE; ++k) {
                float v = te[k];
                pb += v * wl[D_TYPE + k];
                gb += v * wg[D_TYPE + k];
            }
            s_pbi[il] = pb; s_gbi[il] = gb;
        }
    }
    __syncthreads();

    float BLv = __ldg(p_bl);
    float BGv = __ldg(p_bg);

    int jq = tid & 31;       // 32 quads of j (float4)
    int ir = tid >> 5;       // 8 row groups
    int jj = jq * 4;

    float4 tj = *(const float4*)&s_tj[jj];
    float4 pa, ga;
    if (!zero_tile) {
        pa = *(const float4*)&s_paj[jj];
        ga = *(const float4*)&s_gaj[jj];
    }

    size_t base = ((size_t)(off + i0)) * L_SZ + (size_t)(j0 + jj);

#pragma unroll
    for (int r = 0; r < 4; ++r) {
        int il = ir + r * 8;
        float ti = s_ti[il];
        float4 td;
        td.x = fabsf(tj.x - ti);
        td.y = fabsf(tj.y - ti);
        td.z = fabsf(tj.z - ti);
        td.w = fabsf(tj.w - ti);

        float4 sv;
        if (zero_tile) {
            sv = make_float4(0.f, 0.f, 0.f, 0.f);
        } else {
            float pbi = s_pbi[il], gbi = s_gbi[il];
            sv.x = score1(td.x, pa.x, ga.x, pbi, gbi, BLv, BGv);
            sv.y = score1(td.y, pa.y, ga.y, pbi, gbi, BLv, BGv);
            sv.z = score1(td.z, pa.z, ga.z, pbi, gbi, BLv, BGv);
            sv.w = score1(td.w, pa.w, ga.w, pbi, gbi, BLv, BGv);
            if (!full_tile) {
                int i = i0 + il;
                int j = j0 + jj;
                if (j     >= i) sv.x = 0.f;
                if (j + 1 >= i) sv.y = 0.f;
                if (j + 2 >= i) sv.z = 0.f;
                if (j + 3 >= i) sv.w = 0.f;
            }
        }
        size_t ofs = base + (size_t)il * L_SZ;
        __stcs((float4*)(out_scores + ofs), sv);
        __stcs((float4*)(out_tdiff  + ofs), td);
    }
}

extern "C" void kernel_launch(void* const* d_in, const int* in_sizes, int n_in,
                              void* d_out, int out_size) {
    const int*   etype = (const int*)  d_in[0];
    const float* etime = (const float*)d_in[1];
    // d_in[2] = arrival_times (unused by reference)
    const float* Wt    = (const float*)d_in[3];
    const float* temb  = (const float*)d_in[4];
    const float* wl    = (const float*)d_in[5];
    const float* p_bl  = (const float*)d_in[6];
    const float* wg    = (const float*)d_in[7];
    const float* p_bg  = (const float*)d_in[8];

    float* out = (float*)d_out;
    const size_t scoresN = (size_t)B_SZ * L_SZ * L_SZ;
    const size_t hidN    = (size_t)B_SZ * L_SZ * HID;
    float* out_scores = out;
    float* out_hidden = out + scoresN;
    float* out_tdiff  = out + scoresN + hidN;

    dim3 grid(L_SZ / TJ, L_SZ / TI, B_SZ);
    pair_kernel<<<grid, 256>>>(etype, etime, temb, wl, wg, p_bl, p_bg,
                               out_scores, out_tdiff);
    hidden_kernel<<<B_SZ * L_SZ, 256>>>(etype, etime, Wt, temb, out_hidden);
}

// round 3
// speedup vs baseline: 1.4989x; 1.4989x over previous
#include <cuda_runtime.h>
#include <math.h>

#define B_SZ   8
#define L_SZ   2048
#define D_HALF 256
#define D_TYPE 32
#define HID    544          // 512 positional + 32 type
#define TI     32
#define TJ     128

// fp32 constant matching reference: -log(10000.0)/512 rounded to f32
#define DIV_C  (-0.017988946f)

// -------- scratch (no allocations allowed) --------
__device__ float g_pa[B_SZ * L_SZ];
__device__ float g_pb[B_SZ * L_SZ];
__device__ float g_ga[B_SZ * L_SZ];
__device__ float g_gb[B_SZ * L_SZ];
__device__ float g_div[D_HALF];

// -------- prep: per-(b,l) dot products + div_term table (fp32, fast) --------
__global__ void prep_kernel(const int* __restrict__ etype,
                            const float* __restrict__ temb,
                            const float* __restrict__ wl,
                            const float* __restrict__ wg) {
    int idx = blockIdx.x * blockDim.x + threadIdx.x;
    if (idx < D_HALF) {
        // matches ref (f32 exp of f32 product); precise expf, ~2 ulp
        g_div[idx] = expf((float)(2 * idx) * DIV_C);
    }
    if (idx < B_SZ * L_SZ) {
        int et = etype[idx];
        const float* te = temb + et * D_TYPE;
        float pa = 0.f, pb = 0.f, ga = 0.f, gb = 0.f;
#pragma unroll
        for (int k = 0; k < D_TYPE; ++k) {
            float v = te[k];
            pa += v * wl[k];
            pb += v * wl[D_TYPE + k];
            ga += v * wg[k];
            gb += v * wg[D_TYPE + k];
        }
        g_pa[idx] = pa; g_pb[idx] = pb;
        g_ga[idx] = ga; g_gb[idx] = gb;
    }
}

// -------- hidden vector: sin/cos(arc+phi) + type embedding --------
__global__ void __launch_bounds__(256) hidden_kernel(
    const int* __restrict__ etype,
    const float* __restrict__ etime,
    const float* __restrict__ Wt,
    const float* __restrict__ temb,
    float* __restrict__ out_hidden) {
    int bl = blockIdx.x;                 // b*L + l
    int k  = threadIdx.x;                // 0..255
    int l  = bl & (L_SZ - 1);
    float t   = etime[bl];
    float arc = (float)l * g_div[k];     // same fp32 product as reference
    float x   = arc + t * Wt[k];

    // Cody-Waite reduction x mod 2*pi  (|x| < 2100, n < 340)
    float n = rintf(x * 0.15915494309189535f);
    float r = fmaf(n, -6.28125f, x);                    // C1 exact in binary
    r = fmaf(n, -1.9353071795864769e-3f, r);            // C2
    float s, c;
    __sincosf(r, &s, &c);

    float* o = out_hidden + (size_t)bl * HID;
    o[k]           = s;
    o[D_HALF + k]  = c;
    if (k < D_TYPE)
        o[2 * D_HALF + k] = temb[etype[bl] * D_TYPE + k];
}

// -------- scores + t_diff --------
__device__ __forceinline__ float score1(float d, float paj, float gaj,
                                        float pbi, float gbi,
                                        float BLv, float BGv) {
    float xl = paj + pbi + BLv;
    // softplus(xl) = max(xl,0) + log1p(exp(-|xl|))
    float sp = fmaxf(xl, 0.f) + __logf(1.f + __expf(-fabsf(xl)));
    float rl = __fdividef(1.f, sp + 1e-6f);
    float u  = d * rl;
    float kk = 0.4f * __expf(-0.5f * u * u) + 0.3f * __expf(-u);
    float xg = 5.f * (gaj + gbi + BGv);
    float g  = __fdividef(1.f, 1.f + __expf(-xg));
    return g * kk;
}

__global__ void __launch_bounds__(256) pair_kernel(
    const float* __restrict__ etime,
    const float* __restrict__ p_bl,
    const float* __restrict__ p_bg,
    float* __restrict__ out_scores,
    float* __restrict__ out_tdiff) {

    int b  = blockIdx.z;
    int i0 = blockIdx.y * TI;
    int j0 = blockIdx.x * TJ;

    __shared__ float s_tj[TJ], s_paj[TJ], s_gaj[TJ];
    __shared__ float s_ti[TI], s_pbi[TI], s_gbi[TI];

    int tid = threadIdx.x;
    int off = b * L_SZ;
    if (tid < TJ) {
        int j = j0 + tid;
        s_tj[tid]  = etime[off + j];
        s_paj[tid] = g_pa[off + j];
        s_gaj[tid] = g_ga[off + j];
    } else if (tid < TJ + TI) {
        int il = tid - TJ;
        int i  = i0 + il;
        s_ti[il]  = etime[off + i];
        s_pbi[il] = g_pb[off + i];
        s_gbi[il] = g_gb[off + i];
    }
    __syncthreads();

    float BLv = __ldg(p_bl);
    float BGv = __ldg(p_bg);

    int jq = tid & 31;       // 32 quads of j (float4)
    int ir = tid >> 5;       // 8 row groups
    int jj = jq * 4;

    float4 tj = *(const float4*)&s_tj[jj];
    float4 pa = *(const float4*)&s_paj[jj];
    float4 ga = *(const float4*)&s_gaj[jj];

    bool zero_tile = (j0 >= i0 + TI);      // entire tile has j >= i -> scores 0
    bool full_tile = (j0 + TJ <= i0);      // entire tile has j <  i -> no mask

    size_t base = ((size_t)(off + i0)) * L_SZ + (size_t)(j0 + jj);

#pragma unroll
    for (int r = 0; r < 4; ++r) {
        int il = ir + r * 8;
        float ti = s_ti[il];
        float4 td;
        td.x = fabsf(tj.x - ti);
        td.y = fabsf(tj.y - ti);
        td.z = fabsf(tj.z - ti);
        td.w = fabsf(tj.w - ti);

        float4 sv;
        if (zero_tile) {
            sv = make_float4(0.f, 0.f, 0.f, 0.f);
        } else {
            float pbi = s_pbi[il], gbi = s_gbi[il];
            sv.x = score1(td.x, pa.x, ga.x, pbi, gbi, BLv, BGv);
            sv.y = score1(td.y, pa.y, ga.y, pbi, gbi, BLv, BGv);
            sv.z = score1(td.z, pa.z, ga.z, pbi, gbi, BLv, BGv);
            sv.w = score1(td.w, pa.w, ga.w, pbi, gbi, BLv, BGv);
            if (!full_tile) {
                int i = i0 + il;
                int j = j0 + jj;
                if (j     >= i) sv.x = 0.f;
                if (j + 1 >= i) sv.y = 0.f;
                if (j + 2 >= i) sv.z = 0.f;
                if (j + 3 >= i) sv.w = 0.f;
            }
        }
        size_t ofs = base + (size_t)il * L_SZ;
        __stcs((float4*)(out_scores + ofs), sv);
        __stcs((float4*)(out_tdiff  + ofs), td);
    }
}

extern "C" void kernel_launch(void* const* d_in, const int* in_sizes, int n_in,
                              void* d_out, int out_size) {
    const int*   etype = (const int*)  d_in[0];
    const float* etime = (const float*)d_in[1];
    // d_in[2] = arrival_times (unused by reference)
    const float* Wt    = (const float*)d_in[3];
    const float* temb  = (const float*)d_in[4];
    const float* wl    = (const float*)d_in[5];
    const float* p_bl  = (const float*)d_in[6];
    const float* wg    = (const float*)d_in[7];
    const float* p_bg  = (const float*)d_in[8];

    float* out = (float*)d_out;
    const size_t scoresN = (size_t)B_SZ * L_SZ * L_SZ;
    const size_t hidN    = (size_t)B_SZ * L_SZ * HID;
    float* out_scores = out;
    float* out_hidden = out + scoresN;
    float* out_tdiff  = out + scoresN + hidN;

    prep_kernel<<<(B_SZ * L_SZ + 255) / 256, 256>>>(etype, temb, wl, wg);
    hidden_kernel<<<B_SZ * L_SZ, 256>>>(etype, etime, Wt, temb, out_hidden);

    dim3 grid(L_SZ / TJ, L_SZ / TI, B_SZ);
    pair_kernel<<<grid, 256>>>(etime, p_bl, p_bg, out_scores, out_tdiff);
}

// round 4
// speedup vs baseline: 1.6111x; 1.0749x over previous
#include <cuda_runtime.h>
#include <math.h>

#define B_SZ   8
#define L_SZ   2048
#define D_HALF 256
#define D_TYPE 32
#define HID    544          // 512 positional + 32 type
#define NTYPES 21           // NUM_TYPES + 1 (padding row 0)
#define TI     32
#define TJ     128
#define PAIR_BLOCKS (8 * (L_SZ / TI) * (L_SZ / TJ))   // 8192
#define HIDDEN_BLOCKS (B_SZ * L_SZ)                   // 16384

// fp32 constant matching reference: -log(10000.0)/512 rounded to f32
#define DIV_C  (-0.017988946f)

// -------- scratch (no allocations allowed) --------
__device__ float g_div[D_HALF];
__device__ float g_dA[NTYPES];   // te . w_l[:32]   (j side)
__device__ float g_dB[NTYPES];   // te . w_l[32:]   (i side)
__device__ float g_gA[NTYPES];   // te . w_g[:32]
__device__ float g_gB[NTYPES];   // te . w_g[32:]

// -------- micro-prep: div table + per-TYPE dot tables (1 block) --------
__global__ void prep_micro(const float* __restrict__ temb,
                           const float* __restrict__ wl,
                           const float* __restrict__ wg) {
    int t = threadIdx.x;
    // div_term, matches ref: f32 exp of f32 product
    g_div[t] = expf((float)(2 * t) * DIV_C);
    if (t < NTYPES) {
        const float* te = temb + t * D_TYPE;
        float pa = 0.f, pb = 0.f, ga = 0.f, gb = 0.f;
#pragma unroll
        for (int k = 0; k < D_TYPE; ++k) {
            float v = te[k];
            pa += v * wl[k];
            pb += v * wl[D_TYPE + k];
            ga += v * wg[k];
            gb += v * wg[D_TYPE + k];
        }
        g_dA[t] = pa; g_dB[t] = pb;
        g_gA[t] = ga; g_gB[t] = gb;
    }
}

// -------- scores element --------
__device__ __forceinline__ float score1(float d, float paj, float gaj,
                                        float pbi, float gbi,
                                        float BLv, float BGv) {
    float xl = paj + pbi + BLv;
    // softplus(xl) = max(xl,0) + log1p(exp(-|xl|))
    float sp = fmaxf(xl, 0.f) + __logf(1.f + __expf(-fabsf(xl)));
    float rl = __fdividef(1.f, sp + 1e-6f);
    float u  = d * rl;
    float kk = 0.4f * __expf(-0.5f * u * u) + 0.3f * __expf(-u);
    float xg = 5.f * (gaj + gbi + BGv);
    float g  = __fdividef(1.f, 1.f + __expf(-xg));
    return g * kk;
}

// -------- fused: pair tiles (blocks 0..8191) + hidden rows (rest) --------
__global__ void __launch_bounds__(256) fused_kernel(
    const int* __restrict__ etype,
    const float* __restrict__ etime,
    const float* __restrict__ Wt,
    const float* __restrict__ temb,
    const float* __restrict__ p_bl,
    const float* __restrict__ p_bg,
    float* __restrict__ out_scores,
    float* __restrict__ out_hidden,
    float* __restrict__ out_tdiff) {

    int bid = blockIdx.x;
    int tid = threadIdx.x;

    if (bid >= PAIR_BLOCKS) {
        // ---------------- hidden branch ----------------
        int bl = bid - PAIR_BLOCKS;          // b*L + l
        int k  = tid;                        // 0..255
        int l  = bl & (L_SZ - 1);
        float t   = etime[bl];
        float arc = (float)l * g_div[k];     // same fp32 product as reference
        float x   = arc + t * Wt[k];

        // Cody-Waite reduction x mod 2*pi  (|x| < 2100, n < 340)
        float n = rintf(x * 0.15915494309189535f);
        float r = fmaf(n, -6.28125f, x);                 // C1 exact in binary
        r = fmaf(n, -1.9353071795864769e-3f, r);         // C2
        float s, c;
        __sincosf(r, &s, &c);

        float* o = out_hidden + (size_t)bl * HID;
        o[k]           = s;
        o[D_HALF + k]  = c;
        if (k < D_TYPE)
            o[2 * D_HALF + k] = temb[etype[bl] * D_TYPE + k];
        return;
    }

    // ---------------- pair branch ----------------
    int jx = bid & 15;           // 16 tiles of TJ=128
    int iy = (bid >> 4) & 63;    // 64 tiles of TI=32
    int b  = bid >> 10;          // 8 batches
    int i0 = iy * TI;
    int j0 = jx * TJ;

    __shared__ float s_tj[TJ], s_paj[TJ], s_gaj[TJ];
    __shared__ float s_ti[TI], s_pbi[TI], s_gbi[TI];

    int off = b * L_SZ;
    bool zero_tile = (j0 >= i0 + TI);      // entire tile j >= i -> scores 0
    bool full_tile = (j0 + TJ <= i0);      // entire tile j <  i -> no mask

    if (tid < TJ) {
        int j = j0 + tid;
        s_tj[tid] = etime[off + j];
        if (!zero_tile) {
            int et = etype[off + j];
            s_paj[tid] = g_dA[et];
            s_gaj[tid] = g_gA[et];
        }
    } else if (tid < TJ + TI) {
        int il = tid - TJ;
        int i  = i0 + il;
        s_ti[il] = etime[off + i];
        if (!zero_tile) {
            int et = etype[off + i];
            s_pbi[il] = g_dB[et];
            s_gbi[il] = g_gB[et];
        }
    }
    __syncthreads();

    float BLv = __ldg(p_bl);
    float BGv = __ldg(p_bg);

    int jq = tid & 31;       // 32 quads of j (float4)
    int ir = tid >> 5;       // 8 row groups
    int jj = jq * 4;

    float4 tj = *(const float4*)&s_tj[jj];
    float4 pa, ga;
    if (!zero_tile) {
        pa = *(const float4*)&s_paj[jj];
        ga = *(const float4*)&s_gaj[jj];
    }

    size_t base = ((size_t)(off + i0)) * L_SZ + (size_t)(j0 + jj);

#pragma unroll
    for (int r = 0; r < 4; ++r) {
        int il = ir + r * 8;
        float ti = s_ti[il];
        float4 td;
        td.x = fabsf(tj.x - ti);
        td.y = fabsf(tj.y - ti);
        td.z = fabsf(tj.z - ti);
        td.w = fabsf(tj.w - ti);

        float4 sv;
        if (zero_tile) {
            sv = make_float4(0.f, 0.f, 0.f, 0.f);
        } else {
            float pbi = s_pbi[il], gbi = s_gbi[il];
            sv.x = score1(td.x, pa.x, ga.x, pbi, gbi, BLv, BGv);
            sv.y = score1(td.y, pa.y, ga.y, pbi, gbi, BLv, BGv);
            sv.z = score1(td.z, pa.z, ga.z, pbi, gbi, BLv, BGv);
            sv.w = score1(td.w, pa.w, ga.w, pbi, gbi, BLv, BGv);
            if (!full_tile) {
                int i = i0 + il;
                int j = j0 + jj;
                if (j     >= i) sv.x = 0.f;
                if (j + 1 >= i) sv.y = 0.f;
                if (j + 2 >= i) sv.z = 0.f;
                if (j + 3 >= i) sv.w = 0.f;
            }
        }
        size_t ofs = base + (size_t)il * L_SZ;
        __stcs((float4*)(out_scores + ofs), sv);
        __stcs((float4*)(out_tdiff  + ofs), td);
    }
}

extern "C" void kernel_launch(void* const* d_in, const int* in_sizes, int n_in,
                              void* d_out, int out_size) {
    const int*   etype = (const int*)  d_in[0];
    const float* etime = (const float*)d_in[1];
    // d_in[2] = arrival_times (unused by reference)
    const float* Wt    = (const float*)d_in[3];
    const float* temb  = (const float*)d_in[4];
    const float* wl    = (const float*)d_in[5];
    const float* p_bl  = (const float*)d_in[6];
    const float* wg    = (const float*)d_in[7];
    const float* p_bg  = (const float*)d_in[8];

    float* out = (float*)d_out;
    const size_t scoresN = (size_t)B_SZ * L_SZ * L_SZ;
    const size_t hidN    = (size_t)B_SZ * L_SZ * HID;
    float* out_scores = out;
    float* out_hidden = out + scoresN;
    float* out_tdiff  = out + scoresN + hidN;

    prep_micro<<<1, 256>>>(temb, wl, wg);
    fused_kernel<<<PAIR_BLOCKS + HIDDEN_BLOCKS, 256>>>(
        etype, etime, Wt, temb, p_bl, p_bg,
        out_scores, out_hidden, out_tdiff);
}

// round 5
// speedup vs baseline: 1.6568x; 1.0283x over previous
#include <cuda_runtime.h>
#include <math.h>

#define B_SZ   8
#define L_SZ   2048
#define D_HALF 256
#define D_TYPE 32
#define HID    544          // 512 positional + 32 type
#define NTYPES 21           // NUM_TYPES + 1 (padding row 0)
#define NPAIR  (NTYPES * NTYPES)   // 441
#define TI     32
#define TJ     128
#define PAIR_BLOCKS (8 * (L_SZ / TI) * (L_SZ / TJ))   // 8192
#define HIDDEN_BLOCKS (B_SZ * L_SZ)                   // 16384

// fp32 constant matching reference: -log(10000.0)/512 rounded to f32
#define DIV_C  (-0.017988946f)

// -------- scratch (no allocations allowed) --------
__device__ float g_div[D_HALF];
__device__ float g_rl[NPAIR];    // 1/(softplus(pa_j+pb_i+b_l)+eps)  indexed ti*21+tj
__device__ float g_gt[NPAIR];    // sigmoid(5*(ga_j+gb_i+b_g))       indexed ti*21+tj

// -------- micro-prep: div table + per-type-PAIR score tables (1 block) ----
__global__ void prep_micro(const float* __restrict__ temb,
                           const float* __restrict__ wl,
                           const float* __restrict__ wg,
                           const float* __restrict__ p_bl,
                           const float* __restrict__ p_bg) {
    __shared__ float dA[NTYPES], dB[NTYPES], gA[NTYPES], gB[NTYPES];
    int t = threadIdx.x;
    // div_term, matches ref: f32 exp of f32 product
    g_div[t] = expf((float)(2 * t) * DIV_C);
    if (t < NTYPES) {
        const float* te = temb + t * D_TYPE;
        float pa = 0.f, pb = 0.f, ga = 0.f, gb = 0.f;
#pragma unroll
        for (int k = 0; k < D_TYPE; ++k) {
            float v = te[k];
            pa += v * wl[k];
            pb += v * wl[D_TYPE + k];
            ga += v * wg[k];
            gb += v * wg[D_TYPE + k];
        }
        dA[t] = pa; dB[t] = pb;
        gA[t] = ga; gB[t] = gb;
    }
    __syncthreads();
    float BLv = p_bl[0];
    float BGv = p_bg[0];
    for (int p = t; p < NPAIR; p += 256) {
        int ti = p / NTYPES;       // i-side type
        int tj = p - ti * NTYPES;  // j-side type
        // precise softplus: max(x,0) + log1p(exp(-|x|))
        float xl = dA[tj] + dB[ti] + BLv;
        float sp = fmaxf(xl, 0.f) + log1pf(expf(-fabsf(xl)));
        g_rl[p] = 1.f / (sp + 1e-6f);
        float xg = 5.f * (gA[tj] + gB[ti] + BGv);
        g_gt[p] = 1.f / (1.f + expf(-xg));
    }
}

// -------- fused: pair tiles (blocks 0..8191) + hidden rows (rest) --------
__global__ void __launch_bounds__(256) fused_kernel(
    const int* __restrict__ etype,
    const float* __restrict__ etime,
    const float* __restrict__ Wt,
    const float* __restrict__ temb,
    float* __restrict__ out_scores,
    float* __restrict__ out_hidden,
    float* __restrict__ out_tdiff) {

    int bid = blockIdx.x;
    int tid = threadIdx.x;

    if (bid >= PAIR_BLOCKS) {
        // ---------------- hidden branch ----------------
        int bl = bid - PAIR_BLOCKS;          // b*L + l
        int k  = tid;                        // 0..255
        int l  = bl & (L_SZ - 1);
        float t   = etime[bl];
        float arc = (float)l * g_div[k];     // same fp32 product as reference
        float x   = arc + t * Wt[k];

        // Cody-Waite reduction x mod 2*pi  (|x| < 2100, n < 340)
        float n = rintf(x * 0.15915494309189535f);
        float r = fmaf(n, -6.28125f, x);                 // C1 exact in binary
        r = fmaf(n, -1.9353071795864769e-3f, r);         // C2
        float s, c;
        __sincosf(r, &s, &c);

        float* o = out_hidden + (size_t)bl * HID;
        o[k]           = s;
        o[D_HALF + k]  = c;
        if (k < D_TYPE)
            o[2 * D_HALF + k] = temb[etype[bl] * D_TYPE + k];
        return;
    }

    // ---------------- pair branch ----------------
    int jx = bid & 15;           // 16 tiles of TJ=128
    int iy = (bid >> 4) & 63;    // 64 tiles of TI=32
    int b  = bid >> 10;          // 8 batches
    int i0 = iy * TI;
    int j0 = jx * TJ;

    __shared__ float s_tj[TJ], s_ti[TI];
    __shared__ int   s_etj[TJ], s_eti[TI];
    __shared__ float s_rl[NPAIR], s_gt[NPAIR];

    int off = b * L_SZ;
    bool zero_tile = (j0 >= i0 + TI);      // entire tile j >= i -> scores 0
    bool full_tile = (j0 + TJ <= i0);      // entire tile j <  i -> no mask

    if (tid < TJ) {
        int j = j0 + tid;
        s_tj[tid]  = etime[off + j];
        s_etj[tid] = etype[off + j] * 1;   // tj index (column of table)
    } else if (tid < TJ + TI) {
        int il = tid - TJ;
        int i  = i0 + il;
        s_ti[il]  = etime[off + i];
        s_eti[il] = etype[off + i] * NTYPES;   // row base into table
    }
    if (!zero_tile) {
        // stage the 441-entry tables (L2-resident after first wave)
        for (int p = tid; p < NPAIR; p += 256) {
            s_rl[p] = g_rl[p];
            s_gt[p] = g_gt[p];
        }
    }
    __syncthreads();

    int jq = tid & 31;       // 32 quads of j (float4)
    int ir = tid >> 5;       // 8 row groups
    int jj = jq * 4;

    float4 tj = *(const float4*)&s_tj[jj];
    int4   ej = *(const int4*)&s_etj[jj];

    size_t base = ((size_t)(off + i0)) * L_SZ + (size_t)(j0 + jj);

#pragma unroll
    for (int r = 0; r < 4; ++r) {
        int il = ir + r * 8;
        float ti = s_ti[il];
        float4 td;
        td.x = fabsf(tj.x - ti);
        td.y = fabsf(tj.y - ti);
        td.z = fabsf(tj.z - ti);
        td.w = fabsf(tj.w - ti);

        float4 sv;
        if (zero_tile) {
            sv = make_float4(0.f, 0.f, 0.f, 0.f);
        } else {
            int rb = s_eti[il];
            float ux = td.x * s_rl[rb + ej.x];
            float uy = td.y * s_rl[rb + ej.y];
            float uz = td.z * s_rl[rb + ej.z];
            float uw = td.w * s_rl[rb + ej.w];
            sv.x = s_gt[rb + ej.x] *
                   (0.4f * __expf(-0.5f * ux * ux) + 0.3f * __expf(-ux));
            sv.y = s_gt[rb + ej.y] *
                   (0.4f * __expf(-0.5f * uy * uy) + 0.3f * __expf(-uy));
            sv.z = s_gt[rb + ej.z] *
                   (0.4f * __expf(-0.5f * uz * uz) + 0.3f * __expf(-uz));
            sv.w = s_gt[rb + ej.w] *
                   (0.4f * __expf(-0.5f * uw * uw) + 0.3f * __expf(-uw));
            if (!full_tile) {
                int i = i0 + il;
                int j = j0 + jj;
                if (j     >= i) sv.x = 0.f;
                if (j + 1 >= i) sv.y = 0.f;
                if (j + 2 >= i) sv.z = 0.f;
                if (j + 3 >= i) sv.w = 0.f;
            }
        }
        size_t ofs = base + (size_t)il * L_SZ;
        __stcs((float4*)(out_scores + ofs), sv);
        __stcs((float4*)(out_tdiff  + ofs), td);
    }
}

extern "C" void kernel_launch(void* const* d_in, const int* in_sizes, int n_in,
                              void* d_out, int out_size) {
    const int*   etype = (const int*)  d_in[0];
    const float* etime = (const float*)d_in[1];
    // d_in[2] = arrival_times (unused by reference)
    const float* Wt    = (const float*)d_in[3];
    const float* temb  = (const float*)d_in[4];
    const float* wl    = (const float*)d_in[5];
    const float* p_bl  = (const float*)d_in[6];
    const float* wg    = (const float*)d_in[7];
    const float* p_bg  = (const float*)d_in[8];

    float* out = (float*)d_out;
    const size_t scoresN = (size_t)B_SZ * L_SZ * L_SZ;
    const size_t hidN    = (size_t)B_SZ * L_SZ * HID;
    float* out_scores = out;
    float* out_hidden = out + scoresN;
    float* out_tdiff  = out + scoresN + hidN;

    prep_micro<<<1, 256>>>(temb, wl, wg, p_bl, p_bg);
    fused_kernel<<<PAIR_BLOCKS + HIDDEN_BLOCKS, 256>>>(
        etype, etime, Wt, temb,
        out_scores, out_hidden, out_tdiff);
}

// round 6
// speedup vs baseline: 1.7337x; 1.0464x over previous
#include <cuda_runtime.h>
#include <math.h>

#define B_SZ   8
#define L_SZ   2048
#define D_HALF 256
#define D_TYPE 32
#define HID    544          // 512 positional + 32 type
#define NTYPES 21           // NUM_TYPES + 1 (padding row 0)
#define NPAIR  (NTYPES * NTYPES)   // 441
#define TI     64
#define TJ     128
#define PAIR_BLOCKS (B_SZ * (L_SZ / TI) * (L_SZ / TJ))   // 4096
#define HIDDEN_BLOCKS (B_SZ * L_SZ)                      // 16384
#define TOTAL_BLOCKS (PAIR_BLOCKS + HIDDEN_BLOCKS)       // 20480 = 5*4096

// fp32 constant matching reference: -log(10000.0)/512 rounded to f32
#define DIV_C  (-0.017988946f)

// -------- scratch (no allocations allowed) --------
__device__ float  g_div[D_HALF];
__device__ float2 g_tab[NPAIR];   // (rl, gt) indexed ti*21+tj

// -------- micro-prep: div table + per-type-PAIR score tables (1 block) ----
__global__ void prep_micro(const float* __restrict__ temb,
                           const float* __restrict__ wl,
                           const float* __restrict__ wg,
                           const float* __restrict__ p_bl,
                           const float* __restrict__ p_bg) {
    __shared__ float dA[NTYPES], dB[NTYPES], gA[NTYPES], gB[NTYPES];
    int t = threadIdx.x;
    // div_term, matches ref: f32 exp of f32 product
    g_div[t] = expf((float)(2 * t) * DIV_C);
    if (t < NTYPES) {
        const float* te = temb + t * D_TYPE;
        float pa = 0.f, pb = 0.f, ga = 0.f, gb = 0.f;
#pragma unroll
        for (int k = 0; k < D_TYPE; ++k) {
            float v = te[k];
            pa += v * wl[k];
            pb += v * wl[D_TYPE + k];
            ga += v * wg[k];
            gb += v * wg[D_TYPE + k];
        }
        dA[t] = pa; dB[t] = pb;
        gA[t] = ga; gB[t] = gb;
    }
    __syncthreads();
    float BLv = p_bl[0];
    float BGv = p_bg[0];
    for (int p = t; p < NPAIR; p += 256) {
        int ti = p / NTYPES;       // i-side type
        int tj = p - ti * NTYPES;  // j-side type
        // precise softplus: max(x,0) + log1p(exp(-|x|))
        float xl = dA[tj] + dB[ti] + BLv;
        float sp = fmaxf(xl, 0.f) + log1pf(expf(-fabsf(xl)));
        float xg = 5.f * (gA[tj] + gB[ti] + BGv);
        g_tab[p] = make_float2(1.f / (sp + 1e-6f),
                               1.f / (1.f + expf(-xg)));
    }
}

// -------- fused: interleaved pair tiles + hidden rows --------
__global__ void __launch_bounds__(256) fused_kernel(
    const int* __restrict__ etype,
    const float* __restrict__ etime,
    const float* __restrict__ Wt,
    const float* __restrict__ temb,
    float* __restrict__ out_scores,
    float* __restrict__ out_hidden,
    float* __restrict__ out_tdiff) {

    int bid = blockIdx.x;
    int tid = threadIdx.x;
    int p   = bid / 5;
    int rem = bid - p * 5;

    if (rem != 4) {
        // ---------------- hidden branch (4 of every 5 blocks) ----------
        int bl = p * 4 + rem;                // b*L + l
        int k  = tid;                        // 0..255
        int l  = bl & (L_SZ - 1);
        float t   = etime[bl];
        float arc = (float)l * g_div[k];     // same fp32 product as reference
        float x   = arc + t * Wt[k];

        // Cody-Waite reduction x mod 2*pi  (|x| < 2100, n < 340)
        float n = rintf(x * 0.15915494309189535f);
        float r = fmaf(n, -6.28125f, x);                 // C1 exact in binary
        r = fmaf(n, -1.9353071795864769e-3f, r);         // C2
        float s, c;
        __sincosf(r, &s, &c);

        float* o = out_hidden + (unsigned)bl * HID;
        o[k]           = s;
        o[D_HALF + k]  = c;
        if (k < D_TYPE)
            o[2 * D_HALF + k] = temb[etype[bl] * D_TYPE + k];
        return;
    }

    // ---------------- pair branch ----------------
    int jx = p & 15;             // 16 tiles of TJ=128
    int iy = (p >> 4) & 31;      // 32 tiles of TI=64
    int b  = p >> 9;             // 8 batches
    int i0 = iy * TI;
    int j0 = jx * TJ;

    __shared__ float  s_tj[TJ], s_ti[TI];
    __shared__ int    s_etj[TJ], s_eti[TI];
    __shared__ float2 s_tab[NPAIR];

    int off = b * L_SZ;
    bool zero_tile = (j0 >= i0 + TI);      // entire tile j >= i -> scores 0
    bool full_tile = (j0 + TJ <= i0);      // entire tile j <  i -> no mask

    if (tid < TJ) {
        int j = j0 + tid;
        s_tj[tid]  = etime[off + j];
        s_etj[tid] = etype[off + j];
    } else if (tid < TJ + TI) {
        int il = tid - TJ;
        int i  = i0 + il;
        s_ti[il]  = etime[off + i];
        s_eti[il] = etype[off + i] * NTYPES;
    }
    if (!zero_tile) {
        for (int q = tid; q < NPAIR; q += 256)
            s_tab[q] = g_tab[q];
    }
    __syncthreads();

    int jq = tid & 31;       // 32 quads of j (float4)
    int ir = tid >> 5;       // 8 row groups
    int jj = jq * 4;

    float4 tj = *(const float4*)&s_tj[jj];
    int4   ej = *(const int4*)&s_etj[jj];

    unsigned base = (unsigned)(off + i0) * L_SZ + (unsigned)(j0 + jj);

#pragma unroll
    for (int r = 0; r < 8; ++r) {
        int il = ir + r * 8;
        float ti = s_ti[il];
        float4 td;
        td.x = fabsf(tj.x - ti);
        td.y = fabsf(tj.y - ti);
        td.z = fabsf(tj.z - ti);
        td.w = fabsf(tj.w - ti);

        float4 sv;
        if (zero_tile) {
            sv = make_float4(0.f, 0.f, 0.f, 0.f);
        } else {
            int rb = s_eti[il];
            float2 cx = s_tab[rb + ej.x];
            float2 cy = s_tab[rb + ej.y];
            float2 cz = s_tab[rb + ej.z];
            float2 cw = s_tab[rb + ej.w];
            float ux = td.x * cx.x;
            float uy = td.y * cy.x;
            float uz = td.z * cz.x;
            float uw = td.w * cw.x;
            sv.x = cx.y * (0.4f * __expf(-0.5f * ux * ux) + 0.3f * __expf(-ux));
            sv.y = cy.y * (0.4f * __expf(-0.5f * uy * uy) + 0.3f * __expf(-uy));
            sv.z = cz.y * (0.4f * __expf(-0.5f * uz * uz) + 0.3f * __expf(-uz));
            sv.w = cw.y * (0.4f * __expf(-0.5f * uw * uw) + 0.3f * __expf(-uw));
            if (!full_tile) {
                int i = i0 + il;
                int j = j0 + jj;
                if (j     >= i) sv.x = 0.f;
                if (j + 1 >= i) sv.y = 0.f;
                if (j + 2 >= i) sv.z = 0.f;
                if (j + 3 >= i) sv.w = 0.f;
            }
        }
        unsigned ofs = base + (unsigned)il * L_SZ;
        __stcs((float4*)(out_scores + ofs), sv);
        __stcs((float4*)(out_tdiff  + ofs), td);
    }
}

extern "C" void kernel_launch(void* const* d_in, const int* in_sizes, int n_in,
                              void* d_out, int out_size) {
    const int*   etype = (const int*)  d_in[0];
    const float* etime = (const float*)d_in[1];
    // d_in[2] = arrival_times (unused by reference)
    const float* Wt    = (const float*)d_in[3];
    const float* temb  = (const float*)d_in[4];
    const float* wl    = (const float*)d_in[5];
    const float* p_bl  = (const float*)d_in[6];
    const float* wg    = (const float*)d_in[7];
    const float* p_bg  = (const float*)d_in[8];

    float* out = (float*)d_out;
    const size_t scoresN = (size_t)B_SZ * L_SZ * L_SZ;
    const size_t hidN    = (size_t)B_SZ * L_SZ * HID;
    float* out_scores = out;
    float* out_hidden = out + scoresN;
    float* out_tdiff  = out + scoresN + hidN;

    prep_micro<<<1, 256>>>(temb, wl, wg, p_bl, p_bg);
    fused_kernel<<<TOTAL_BLOCKS, 256>>>(
        etype, etime, Wt, temb,
        out_scores, out_hidden, out_tdiff);
}

// round 7
// speedup vs baseline: 1.7484x; 1.0085x over previous
#include <cuda_runtime.h>
#include <math.h>

#define B_SZ   8
#define L_SZ   2048
#define D_HALF 256
#define D_TYPE 32
#define HID    544          // 512 positional + 32 type
#define NTYPES 21           // NUM_TYPES + 1 (padding row 0)
#define NPAIR  (NTYPES * NTYPES)   // 441
#define TI     64
#define TJ     128
#define HROWS  8            // hidden rows per block
#define PAIR_BLOCKS (B_SZ * (L_SZ / TI) * (L_SZ / TJ))   // 4096
#define HIDDEN_BLOCKS (B_SZ * L_SZ / HROWS)              // 2048
#define TOTAL_BLOCKS (PAIR_BLOCKS + HIDDEN_BLOCKS)       // 6144 = 3*2048

// fp32 constant matching reference: -log(10000.0)/512 rounded to f32
#define DIV_C  (-0.017988946f)

// -------- scratch (no allocations allowed) --------
__device__ float  g_div[D_HALF];
__device__ float2 g_tab[NPAIR];   // (rl, gt) indexed ti*21+tj

// -------- micro-prep: div table + per-type-PAIR score tables (1 block) ----
__global__ void prep_micro(const float* __restrict__ temb,
                           const float* __restrict__ wl,
                           const float* __restrict__ wg,
                           const float* __restrict__ p_bl,
                           const float* __restrict__ p_bg) {
    __shared__ float dA[NTYPES], dB[NTYPES], gA[NTYPES], gB[NTYPES];
    int t = threadIdx.x;
    // div_term, matches ref: f32 exp of f32 product
    g_div[t] = expf((float)(2 * t) * DIV_C);
    if (t < NTYPES) {
        const float* te = temb + t * D_TYPE;
        float pa = 0.f, pb = 0.f, ga = 0.f, gb = 0.f;
#pragma unroll
        for (int k = 0; k < D_TYPE; ++k) {
            float v = te[k];
            pa += v * wl[k];
            pb += v * wl[D_TYPE + k];
            ga += v * wg[k];
            gb += v * wg[D_TYPE + k];
        }
        dA[t] = pa; dB[t] = pb;
        gA[t] = ga; gB[t] = gb;
    }
    __syncthreads();
    float BLv = p_bl[0];
    float BGv = p_bg[0];
    for (int p = t; p < NPAIR; p += 256) {
        int ti = p / NTYPES;       // i-side type
        int tj = p - ti * NTYPES;  // j-side type
        // precise softplus: max(x,0) + log1p(exp(-|x|))
        float xl = dA[tj] + dB[ti] + BLv;
        float sp = fmaxf(xl, 0.f) + log1pf(expf(-fabsf(xl)));
        float xg = 5.f * (gA[tj] + gB[ti] + BGv);
        g_tab[p] = make_float2(1.f / (sp + 1e-6f),
                               1.f / (1.f + expf(-xg)));
    }
}

// -------- fused: interleaved pair tiles + multi-row hidden blocks --------
__global__ void __launch_bounds__(256) fused_kernel(
    const int* __restrict__ etype,
    const float* __restrict__ etime,
    const float* __restrict__ Wt,
    const float* __restrict__ temb,
    float* __restrict__ out_scores,
    float* __restrict__ out_hidden,
    float* __restrict__ out_tdiff) {

    int bid = blockIdx.x;
    int tid = threadIdx.x;
    int q   = bid / 3;
    int rem = bid - q * 3;

    if (rem == 2) {
        // ---------------- hidden branch: HROWS positions per block -------
        int bl0 = q * HROWS;                 // first b*L + l of this block
        int k   = tid;                       // 0..255
        float dv = g_div[k];                 // load once, reuse 8x
        float wt = Wt[k];
        float* o = out_hidden + (unsigned)bl0 * HID + k;
#pragma unroll
        for (int rr = 0; rr < HROWS; ++rr) {
            int bl = bl0 + rr;
            int l  = bl & (L_SZ - 1);
            float t   = etime[bl];
            float arc = (float)l * dv;       // same fp32 product as reference
            float x   = arc + t * wt;

            // Cody-Waite reduction x mod 2*pi  (|x| < 2100, n < 340)
            float n = rintf(x * 0.15915494309189535f);
            float r = fmaf(n, -6.28125f, x);             // C1 exact in binary
            r = fmaf(n, -1.9353071795864769e-3f, r);     // C2
            float s, c;
            __sincosf(r, &s, &c);

            o[0]      = s;
            o[D_HALF] = c;
            if (k < D_TYPE)
                o[2 * D_HALF] = temb[etype[bl] * D_TYPE + k];
            o += HID;
        }
        return;
    }

    // ---------------- pair branch ----------------
    int p  = q * 2 + rem;        // 0..4095
    int jx = p & 15;             // 16 tiles of TJ=128
    int iy = (p >> 4) & 31;      // 32 tiles of TI=64
    int b  = p >> 9;             // 8 batches
    int i0 = iy * TI;
    int j0 = jx * TJ;

    __shared__ float  s_tj[TJ], s_ti[TI];
    __shared__ int    s_etj[TJ], s_eti[TI];
    __shared__ float2 s_tab[NPAIR];

    int off = b * L_SZ;
    bool zero_tile = (j0 >= i0 + TI);      // entire tile j >= i -> scores 0
    bool full_tile = (j0 + TJ <= i0);      // entire tile j <  i -> no mask

    if (tid < TJ) {
        int j = j0 + tid;
        s_tj[tid]  = etime[off + j];
        s_etj[tid] = etype[off + j];
    } else if (tid < TJ + TI) {
        int il = tid - TJ;
        int i  = i0 + il;
        s_ti[il]  = etime[off + i];
        s_eti[il] = etype[off + i] * NTYPES;
    }
    if (!zero_tile) {
        for (int w = tid; w < NPAIR; w += 256)
            s_tab[w] = g_tab[w];
    }
    __syncthreads();

    int jq = tid & 31;       // 32 quads of j (float4)
    int ir = tid >> 5;       // 8 row groups
    int jj = jq * 4;

    float4 tj = *(const float4*)&s_tj[jj];
    int4   ej = *(const int4*)&s_etj[jj];

    unsigned base = (unsigned)(off + i0) * L_SZ + (unsigned)(j0 + jj);

#pragma unroll
    for (int r = 0; r < 8; ++r) {
        int il = ir + r * 8;
        float ti = s_ti[il];
        float4 td;
        td.x = fabsf(tj.x - ti);
        td.y = fabsf(tj.y - ti);
        td.z = fabsf(tj.z - ti);
        td.w = fabsf(tj.w - ti);

        float4 sv;
        if (zero_tile) {
            sv = make_float4(0.f, 0.f, 0.f, 0.f);
        } else {
            int rb = s_eti[il];
            float2 cx = s_tab[rb + ej.x];
            float2 cy = s_tab[rb + ej.y];
            float2 cz = s_tab[rb + ej.z];
            float2 cw = s_tab[rb + ej.w];
            float ux = td.x * cx.x;
            float uy = td.y * cy.x;
            float uz = td.z * cz.x;
            float uw = td.w * cw.x;
            sv.x = cx.y * (0.4f * __expf(-0.5f * ux * ux) + 0.3f * __expf(-ux));
            sv.y = cy.y * (0.4f * __expf(-0.5f * uy * uy) + 0.3f * __expf(-uy));
            sv.z = cz.y * (0.4f * __expf(-0.5f * uz * uz) + 0.3f * __expf(-uz));
            sv.w = cw.y * (0.4f * __expf(-0.5f * uw * uw) + 0.3f * __expf(-uw));
            if (!full_tile) {
                int i = i0 + il;
                int j = j0 + jj;
                if (j     >= i) sv.x = 0.f;
                if (j + 1 >= i) sv.y = 0.f;
                if (j + 2 >= i) sv.z = 0.f;
                if (j + 3 >= i) sv.w = 0.f;
            }
        }
        unsigned ofs = base + (unsigned)il * L_SZ;
        __stcs((float4*)(out_scores + ofs), sv);
        __stcs((float4*)(out_tdiff  + ofs), td);
    }
}

extern "C" void kernel_launch(void* const* d_in, const int* in_sizes, int n_in,
                              void* d_out, int out_size) {
    const int*   etype = (const int*)  d_in[0];
    const float* etime = (const float*)d_in[1];
    // d_in[2] = arrival_times (unused by reference)
    const float* Wt    = (const float*)d_in[3];
    const float* temb  = (const float*)d_in[4];
    const float* wl    = (const float*)d_in[5];
    const float* p_bl  = (const float*)d_in[6];
    const float* wg    = (const float*)d_in[7];
    const float* p_bg  = (const float*)d_in[8];

    float* out = (float*)d_out;
    const size_t scoresN = (size_t)B_SZ * L_SZ * L_SZ;
    const size_t hidN    = (size_t)B_SZ * L_SZ * HID;
    float* out_scores = out;
    float* out_hidden = out + scoresN;
    float* out_tdiff  = out + scoresN + hidN;

    prep_micro<<<1, 256>>>(temb, wl, wg, p_bl, p_bg);
    fused_kernel<<<TOTAL_BLOCKS, 256>>>(
        etype, etime, Wt, temb,
        out_scores, out_hidden, out_tdiff);
}

// round 8
// speedup vs baseline: 1.8218x; 1.0420x over previous
#include <cuda_runtime.h>
#include <math.h>

#define B_SZ   8
#define L_SZ   2048
#define D_HALF 256
#define D_TYPE 32
#define HID    544          // 512 positional + 32 type
#define NTYPES 21           // NUM_TYPES + 1 (padding row 0)
#define NPAIR  (NTYPES * NTYPES)   // 441
#define TI     64
#define TJ     128
#define HROWS  8            // hidden rows per block
#define PAIR_BLOCKS (B_SZ * (L_SZ / TI) * (L_SZ / TJ))   // 4096
#define HIDDEN_BLOCKS (B_SZ * L_SZ / HROWS)              // 2048
#define TOTAL_BLOCKS (PAIR_BLOCKS + HIDDEN_BLOCKS)       // 6144 = 3*2048

// fp32 constant matching reference: -log(10000.0)/512 rounded to f32
#define DIV_C  (-0.017988946f)

// -------- fused single launch: pair tiles + multi-row hidden blocks ------
__global__ void __launch_bounds__(256) fused_kernel(
    const int* __restrict__ etype,
    const float* __restrict__ etime,
    const float* __restrict__ Wt,
    const float* __restrict__ temb,
    const float* __restrict__ wl,
    const float* __restrict__ wg,
    const float* __restrict__ p_bl,
    const float* __restrict__ p_bg,
    float* __restrict__ out_scores,
    float* __restrict__ out_hidden,
    float* __restrict__ out_tdiff) {

    int bid = blockIdx.x;
    int tid = threadIdx.x;
    int q   = bid / 3;
    int rem = bid - q * 3;

    if (rem == 2) {
        // ---------------- hidden branch: HROWS positions per block -------
        int bl0 = q * HROWS;                 // first b*L + l of this block
        int k   = tid;                       // 0..255
        // div_term, matches ref: f32 exp of f32 product (precise expf)
        float dv = expf((float)(2 * k) * DIV_C);
        float wt = Wt[k];
        float* o = out_hidden + (unsigned)bl0 * HID + k;
#pragma unroll
        for (int rr = 0; rr < HROWS; ++rr) {
            int bl = bl0 + rr;
            int l  = bl & (L_SZ - 1);
            float t   = etime[bl];
            float arc = (float)l * dv;       // same fp32 product as reference
            float x   = arc + t * wt;

            // Cody-Waite reduction x mod 2*pi  (|x| < 2100, n < 340)
            float n = rintf(x * 0.15915494309189535f);
            float r = fmaf(n, -6.28125f, x);             // C1 exact in binary
            r = fmaf(n, -1.9353071795864769e-3f, r);     // C2
            float s, c;
            __sincosf(r, &s, &c);

            o[0]      = s;
            o[D_HALF] = c;
            if (k < D_TYPE)
                o[2 * D_HALF] = temb[etype[bl] * D_TYPE + k];
            o += HID;
        }
        return;
    }

    // ---------------- pair branch ----------------
    int p  = q * 2 + rem;        // 0..4095
    int jx = p & 15;             // 16 tiles of TJ=128
    int iy = (p >> 4) & 31;      // 32 tiles of TI=64
    int b  = p >> 9;             // 8 batches
    int i0 = iy * TI;
    int j0 = jx * TJ;

    __shared__ float  s_tj[TJ], s_ti[TI];
    __shared__ int    s_etj[TJ], s_eti[TI];
    __shared__ float  dA[NTYPES], dB[NTYPES], gA[NTYPES], gB[NTYPES];
    __shared__ float2 s_tab[NPAIR];

    int off = b * L_SZ;
    bool zero_tile = (j0 >= i0 + TI);      // entire tile j >= i -> scores 0
    bool full_tile = (j0 + TJ <= i0);      // entire tile j <  i -> no mask

    if (tid < TJ) {
        int j = j0 + tid;
        s_tj[tid]  = etime[off + j];
        s_etj[tid] = etype[off + j];
    } else if (tid < TJ + TI) {
        int il = tid - TJ;
        int i  = i0 + il;
        s_ti[il]  = etime[off + i];
        s_eti[il] = etype[off + i] * NTYPES;
    }

    if (!zero_tile) {
        // ---- per-block table build (replaces prep kernel) ----
        if (tid < 4 * NTYPES) {
            int ty    = tid >> 2;            // type 0..20
            int which = tid & 3;             // 0:dA 1:dB 2:gA 3:gB
            const float* te = temb + ty * D_TYPE;
            const float* w  = (which < 2 ? wl : wg) + (which & 1) * D_TYPE;
            float acc = 0.f;
#pragma unroll
            for (int k = 0; k < D_TYPE; ++k) acc += te[k] * w[k];
            if      (which == 0) dA[ty] = acc;
            else if (which == 1) dB[ty] = acc;
            else if (which == 2) gA[ty] = acc;
            else                 gB[ty] = acc;
        }
        __syncthreads();
        float BLv = __ldg(p_bl);
        float BGv = __ldg(p_bg);
        for (int w = tid; w < NPAIR; w += 256) {
            int t_i = w / NTYPES;
            int t_j = w - t_i * NTYPES;
            float xl = dA[t_j] + dB[t_i] + BLv;
            float sp = fmaxf(xl, 0.f) + __logf(1.f + __expf(-fabsf(xl)));
            float xg = 5.f * (gA[t_j] + gB[t_i] + BGv);
            s_tab[w] = make_float2(__fdividef(1.f, sp + 1e-6f),
                                   __fdividef(1.f, 1.f + __expf(-xg)));
        }
    } else {
        __syncthreads();   // keep barrier counts uniform per block
    }
    __syncthreads();

    int jq = tid & 31;       // 32 quads of j (float4)
    int ir = tid >> 5;       // 8 row groups
    int jj = jq * 4;

    float4 tj = *(const float4*)&s_tj[jj];
    int4   ej = *(const int4*)&s_etj[jj];

    unsigned base = (unsigned)(off + i0) * L_SZ + (unsigned)(j0 + jj);

#pragma unroll
    for (int r = 0; r < 8; ++r) {
        int il = ir + r * 8;
        float ti = s_ti[il];
        float4 td;
        td.x = fabsf(tj.x - ti);
        td.y = fabsf(tj.y - ti);
        td.z = fabsf(tj.z - ti);
        td.w = fabsf(tj.w - ti);

        float4 sv;
        if (zero_tile) {
            sv = make_float4(0.f, 0.f, 0.f, 0.f);
        } else {
            int rb = s_eti[il];
            float2 cx = s_tab[rb + ej.x];
            float2 cy = s_tab[rb + ej.y];
            float2 cz = s_tab[rb + ej.z];
            float2 cw = s_tab[rb + ej.w];
            float ux = td.x * cx.x;
            float uy = td.y * cy.x;
            float uz = td.z * cz.x;
            float uw = td.w * cw.x;
            sv.x = cx.y * (0.4f * __expf(-0.5f * ux * ux) + 0.3f * __expf(-ux));
            sv.y = cy.y * (0.4f * __expf(-0.5f * uy * uy) + 0.3f * __expf(-uy));
            sv.z = cz.y * (0.4f * __expf(-0.5f * uz * uz) + 0.3f * __expf(-uz));
            sv.w = cw.y * (0.4f * __expf(-0.5f * uw * uw) + 0.3f * __expf(-uw));
            if (!full_tile) {
                int i = i0 + il;
                int j = j0 + jj;
                if (j     >= i) sv.x = 0.f;
                if (j + 1 >= i) sv.y = 0.f;
                if (j + 2 >= i) sv.z = 0.f;
                if (j + 3 >= i) sv.w = 0.f;
            }
        }
        unsigned ofs = base + (unsigned)il * L_SZ;
        __stcs((float4*)(out_scores + ofs), sv);
        __stcs((float4*)(out_tdiff  + ofs), td);
    }
}

extern "C" void kernel_launch(void* const* d_in, const int* in_sizes, int n_in,
                              void* d_out, int out_size) {
    const int*   etype = (const int*)  d_in[0];
    const float* etime = (const float*)d_in[1];
    // d_in[2] = arrival_times (unused by reference)
    const float* Wt    = (const float*)d_in[3];
    const float* temb  = (const float*)d_in[4];
    const float* wl    = (const float*)d_in[5];
    const float* p_bl  = (const float*)d_in[6];
    const float* wg    = (const float*)d_in[7];
    const float* p_bg  = (const float*)d_in[8];

    float* out = (float*)d_out;
    const size_t scoresN = (size_t)B_SZ * L_SZ * L_SZ;
    const size_t hidN    = (size_t)B_SZ * L_SZ * HID;
    float* out_scores = out;
    float* out_hidden = out + scoresN;
    float* out_tdiff  = out + scoresN + hidN;

    fused_kernel<<<TOTAL_BLOCKS, 256>>>(
        etype, etime, Wt, temb, wl, wg, p_bl, p_bg,
        out_scores, out_hidden, out_tdiff);
}